// round 16
// baseline (speedup 1.0000x reference)
#include <cuda_runtime.h>

// FFJORD: 2 chained fixed-step DOPRI5 integrations of a (64+1)->256->256->64 MLP.
// One CTA integrates 16 batch rows. fp32 via fma.rn.f32x2.
// R16 = R15 + bank-conflict-free column swizzle: smem activation buffers index
// columns via phys(c) = ((c&7)<<s)|(c>>3). Epilogue STS conflicts 16-way -> 2,
// glue 8-way -> 4, sY 32-way -> 4. k-loops restructured into aligned blocks of
// 8 so the swizzled load offsets fold into compile-time immediates.

typedef unsigned long long u64;

#define Dd     64
#define Hh     256
#define MROWS  16
#define STRA   20      // row stride in floats (per physical column)
#define NT     128
#define NSTEPS 16
#define NCTAS  (4096 / MROWS)   // 256

// column swizzles (bijective)
#define PHYS6(c) ((((c) & 7) << 3) | ((c) >> 3))          // 64-col buffers
#define PHYS8(c) ((((c) & 7) << 5) | ((c) >> 3))          // 256-col buffers
#define INSTEP6  (8  * STRA)   // words between consecutive (k&7) in 64-col buf
#define INSTEP8  (32 * STRA)   // words between consecutive (k&7) in 256-col buf

// smem: sZ[64*STRA] + sH1[256*STRA] + sH2[256*STRA] + sY[64*STRA]
//       + sK[6*64*STRA] + sPart[4*64 ulonglong2]
#define SM_FLOATS ((Dd + Hh + Hh + Dd + 6*Dd) * STRA)
#define SM_BYTES  (SM_FLOATS * 4 + 4 * 64 * 16)   // ~86 KB -> 2 CTAs/SM

struct FfjordParams {
    const float* W1[2]; const float* b1[2];
    const float* W2[2]; const float* b2[2];
    const float* W3[2]; const float* b3[2];
};

__device__ __forceinline__ u64 dup2(float v) {
    u64 r; asm("mov.b64 %0, {%1, %1};" : "=l"(r) : "r"(__float_as_uint(v)));
    return r;
}
__device__ __forceinline__ void fma2(u64& d, u64 a, u64 b) {
    asm("fma.rn.f32x2 %0, %1, %2, %3;" : "=l"(d) : "l"(a), "l"(b), "l"(d));
}
__device__ __forceinline__ u64 add2(u64 a, u64 b) {
    u64 r; asm("add.rn.f32x2 %0, %1, %2;" : "=l"(r) : "l"(a), "l"(b)); return r;
}
__device__ __forceinline__ float lo32(u64 v){ return __uint_as_float((unsigned)v); }
__device__ __forceinline__ float hi32(u64 v){ return __uint_as_float((unsigned)(v>>32)); }

__device__ __forceinline__ float4 ldg4(const float* p) {
    float4 v;
    asm("ld.global.nc.v4.f32 {%0,%1,%2,%3}, [%4];"
        : "=f"(v.x), "=f"(v.y), "=f"(v.z), "=f"(v.w) : "l"(p));
    return v;
}
__device__ __forceinline__ float2 ldg2f(const float* p) {
    float2 v;
    asm("ld.global.nc.v2.f32 {%0,%1}, [%2];" : "=f"(v.x), "=f"(v.y) : "l"(p));
    return v;
}

__device__ __forceinline__ float fast_tanh(float x) {
    float r; asm("tanh.approx.f32 %0, %1;" : "=f"(r) : "f"(x)); return r;
}

__device__ __forceinline__ float4 f4_fma(float c, float4 a, float4 acc) {
    return make_float4(fmaf(c, a.x, acc.x), fmaf(c, a.y, acc.y),
                       fmaf(c, a.z, acc.z), fmaf(c, a.w, acc.w));
}

__constant__ float DP_A[6][5] = {
    { 0.f, 0.f, 0.f, 0.f, 0.f },
    { 1.f/5.f, 0.f, 0.f, 0.f, 0.f },
    { 3.f/40.f, 9.f/40.f, 0.f, 0.f, 0.f },
    { 44.f/45.f, -56.f/15.f, 32.f/9.f, 0.f, 0.f },
    { 19372.f/6561.f, -25360.f/2187.f, 64448.f/6561.f, -212.f/729.f, 0.f },
    { 9017.f/3168.f, -355.f/33.f, 46732.f/5247.f, 49.f/176.f, -5103.f/18656.f },
};
__constant__ float DP_C[6] = { 0.f, 1.f/5.f, 3.f/10.f, 4.f/5.f, 8.f/9.f, 1.f };
__constant__ float DP_B[6] = { 35.f/384.f, 0.f, 500.f/1113.f, 125.f/192.f,
                               -2187.f/6784.f, 11.f/84.f };

#define LOAD_AB(dst, ptr) do { \
    ulonglong2 _t0 = *(const ulonglong2*)(ptr); \
    ulonglong2 _t1 = *(const ulonglong2*)((ptr) + 4); \
    (dst)[0] = _t0.x; (dst)[1] = _t0.y; (dst)[2] = _t1.x; (dst)[3] = _t1.y; \
} while (0)

#define FMA16() do { \
    fma2(acc[0][0], a0, wA); fma2(acc[0][1], a0, wB); \
    fma2(acc[0][2], a0, wC); fma2(acc[0][3], a0, wD); \
    fma2(acc[1][0], a1, wA); fma2(acc[1][1], a1, wB); \
    fma2(acc[1][2], a1, wC); fma2(acc[1][3], a1, wD); \
    fma2(acc[2][0], a2, wA); fma2(acc[2][1], a2, wB); \
    fma2(acc[2][2], a2, wC); fma2(acc[2][3], a2, wD); \
    fma2(acc[3][0], a3, wA); fma2(acc[3][1], a3, wB); \
    fma2(acc[3][2], a3, wC); fma2(acc[3][3], a3, wD); \
} while (0)

// N=256 layer. 4 warps: rowgroup rg=w&1 (rows 8*rg..+7), colgroup g=w>>1
// (cols 128*g + 4*lane..+3). Input columns swizzled with step INSTEP words;
// output written at PHYS8 columns. Blocked-by-8 k-loop: swizzle offsets fold.
template<int K, int INSTEP, bool TANH, bool TFOLD>
__device__ __forceinline__ void dense256(
    const float* __restrict__ W, const float* __restrict__ bias,
    const float* __restrict__ tw, float t,
    const float* __restrict__ sA, float* __restrict__ sOut,
    int lane, int g, int r0)
{
    u64 acc[4][4];
    {
        float4 b = *(const float4*)(bias + 128*g + 4*lane);
        if (TFOLD) {
            float4 wt = ldg4(tw + 128*g + 4*lane);
            b.x = fmaf(t, wt.x, b.x); b.y = fmaf(t, wt.y, b.y);
            b.z = fmaf(t, wt.z, b.z); b.w = fmaf(t, wt.w, b.w);
        }
        u64 b0 = dup2(b.x), b1 = dup2(b.y), b2 = dup2(b.z), b3 = dup2(b.w);
#pragma unroll
        for (int q = 0; q < 4; q++) {
            acc[q][0] = b0; acc[q][1] = b1; acc[q][2] = b2; acc[q][3] = b3;
        }
    }

    const float* wrow  = W + 128*g + 4*lane;
    const float* aBlk  = sA + r0;

    float4 wb[8];
#pragma unroll
    for (int s = 0; s < 8; s++) wb[s] = ldg4(wrow + s*Hh);
    const float* wNext = wrow + 8*Hh;

    u64 ab[2][4];
    LOAD_AB(ab[0], aBlk);
    LOAD_AB(ab[1], aBlk + INSTEP);

    for (int kb = 0; kb < K - 8; kb += 8) {
#pragma unroll
        for (int i = 0; i < 8; i++) {
            float4 wf = wb[i];
            wb[i] = ldg4(wNext + i*Hh);
            const int pb = i & 1;
            u64 a0 = ab[pb][0], a1 = ab[pb][1], a2 = ab[pb][2], a3 = ab[pb][3];
            {   // prefetch k+2 (compile-time offsets per instance)
                const float* ap = aBlk + ((i+2)&7)*INSTEP + ((i+2)>>3)*STRA;
                LOAD_AB(ab[pb], ap);
            }
            u64 wA = dup2(wf.x), wB = dup2(wf.y), wC = dup2(wf.z), wD = dup2(wf.w);
            FMA16();
        }
        wNext += 8*Hh;
        aBlk  += STRA;
    }
    // last block (ring already holds K-8..K-1)
#pragma unroll
    for (int i = 0; i < 8; i++) {
        float4 wf = wb[i];
        const int pb = i & 1;
        u64 a0 = ab[pb][0], a1 = ab[pb][1], a2 = ab[pb][2], a3 = ab[pb][3];
        if (i < 6) {
            const float* ap = aBlk + ((i+2)&7)*INSTEP + ((i+2)>>3)*STRA;
            LOAD_AB(ab[pb], ap);
        }
        u64 wA = dup2(wf.x), wB = dup2(wf.y), wC = dup2(wf.z), wD = dup2(wf.w);
        FMA16();
    }

    // epilogue: col = 128g + 4*lane + c  ->  PHYS8 column; N~2 conflicts
    const int pc    = 4 * (lane & 1);          // (col&7) - c
    const int pbase = 16*g + (lane >> 1);      // col >> 3
#pragma unroll
    for (int c = 0; c < 4; c++) {
        const int phys = ((pc + c) << 5) + pbase;
        float v[8];
#pragma unroll
        for (int q = 0; q < 4; q++) {
            v[2*q]   = lo32(acc[q][c]);
            v[2*q+1] = hi32(acc[q][c]);
        }
        if (TANH) {
#pragma unroll
            for (int r = 0; r < 8; r++) v[r] = fast_tanh(v[r]);
        }
        float* o = sOut + phys*STRA + r0;
        *(float4*)(o)     = make_float4(v[0], v[1], v[2], v[3]);
        *(float4*)(o + 4) = make_float4(v[4], v[5], v[6], v[7]);
    }
}

// N=64 output layer (K=256), SPLIT-K + fused RK glue, swizzled columns.
// Warp w: rg=w&1 -> rows 8*rg..+7; kg=w>>1 -> k in [128*kg, 128*kg+128).
// kg1 stores f32x2 partials; kg0 reduces + k-store + Z/y glue (PHYS6 cols).
__device__ __forceinline__ void dense64_splitk_fused(
    const float* __restrict__ W, const float* __restrict__ bias,
    const float* __restrict__ sA, float* __restrict__ sK,
    float* __restrict__ sY, float* __restrict__ sZ,
    ulonglong2* __restrict__ sPart,
    const float cf[5], float cfr, int s, bool writeY,
    int lane, int rg, int kg)
{
    const int r0d = rg * 8;
    u64 acc[4][2];
    if (kg == 0) {
        float2 bb = *(const float2*)(bias + 2*lane);
        u64 b0 = dup2(bb.x), b1 = dup2(bb.y);
#pragma unroll
        for (int q = 0; q < 4; q++) { acc[q][0] = b0; acc[q][1] = b1; }
    } else {
#pragma unroll
        for (int q = 0; q < 4; q++) { acc[q][0] = 0ull; acc[q][1] = 0ull; }
    }

    const int kbeg = kg * 128;
    const float* wrow = W + kbeg*Dd + 2*lane;
    const float* aBlk = sA + (kbeg >> 3)*STRA + r0d;

    float2 wb[8];
#pragma unroll
    for (int q = 0; q < 8; q++) wb[q] = ldg2f(wrow + q*Dd);
    const float* wNext = wrow + 8*Dd;

    u64 ab[2][4];
    LOAD_AB(ab[0], aBlk);
    LOAD_AB(ab[1], aBlk + INSTEP8);

    for (int kb = 0; kb < 120; kb += 8) {
#pragma unroll
        for (int i = 0; i < 8; i++) {
            float2 wf = wb[i];
            wb[i] = ldg2f(wNext + i*Dd);
            const int pb = i & 1;
            u64 a0 = ab[pb][0], a1 = ab[pb][1], a2 = ab[pb][2], a3 = ab[pb][3];
            {
                const float* ap = aBlk + ((i+2)&7)*INSTEP8 + ((i+2)>>3)*STRA;
                LOAD_AB(ab[pb], ap);
            }
            u64 wA = dup2(wf.x), wB = dup2(wf.y);
            fma2(acc[0][0], a0, wA); fma2(acc[0][1], a0, wB);
            fma2(acc[1][0], a1, wA); fma2(acc[1][1], a1, wB);
            fma2(acc[2][0], a2, wA); fma2(acc[2][1], a2, wB);
            fma2(acc[3][0], a3, wA); fma2(acc[3][1], a3, wB);
        }
        wNext += 8*Dd;
        aBlk  += STRA;
    }
#pragma unroll
    for (int i = 0; i < 8; i++) {
        float2 wf = wb[i];
        const int pb = i & 1;
        u64 a0 = ab[pb][0], a1 = ab[pb][1], a2 = ab[pb][2], a3 = ab[pb][3];
        if (i < 6) {
            const float* ap = aBlk + ((i+2)&7)*INSTEP8 + ((i+2)>>3)*STRA;
            LOAD_AB(ab[pb], ap);
        }
        u64 wA = dup2(wf.x), wB = dup2(wf.y);
        fma2(acc[0][0], a0, wA); fma2(acc[0][1], a0, wB);
        fma2(acc[1][0], a1, wA); fma2(acc[1][1], a1, wB);
        fma2(acc[2][0], a2, wA); fma2(acc[2][1], a2, wB);
        fma2(acc[3][0], a3, wA); fma2(acc[3][1], a3, wB);
    }

    const int p = rg*32 + lane;
    if (kg == 1) {
#pragma unroll
        for (int j = 0; j < 4; j++)
            sPart[j*64 + p] = make_ulonglong2(acc[j][0], acc[j][1]);
    }
    __syncthreads();

    if (kg == 0) {
#pragma unroll
        for (int j = 0; j < 4; j++) {
            ulonglong2 t = sPart[j*64 + p];
            acc[j][0] = add2(acc[j][0], t.x);
            acc[j][1] = add2(acc[j][1], t.y);
        }

        // swizzled column indices for cols c0=2*lane, c1=2*lane+1
        const int ph0 = (((2*lane)     & 7) << 3) | (lane >> 2);
        const int ph1 = (((2*lane + 1) & 7) << 3) | (lane >> 2);

        float4 v0a = make_float4(lo32(acc[0][0]), hi32(acc[0][0]),
                                 lo32(acc[1][0]), hi32(acc[1][0]));
        float4 v0b = make_float4(lo32(acc[2][0]), hi32(acc[2][0]),
                                 lo32(acc[3][0]), hi32(acc[3][0]));
        float4 v1a = make_float4(lo32(acc[0][1]), hi32(acc[0][1]),
                                 lo32(acc[1][1]), hi32(acc[1][1]));
        float4 v1b = make_float4(lo32(acc[2][1]), hi32(acc[2][1]),
                                 lo32(acc[3][1]), hi32(acc[3][1]));

        if (s < 5) {
            float* kd = sK + s * Dd * STRA;
            float* p0 = kd + ph0*STRA + r0d;
            float* p1 = kd + ph1*STRA + r0d;
            *(float4*)(p0) = v0a; *(float4*)(p0+4) = v0b;
            *(float4*)(p1) = v1a; *(float4*)(p1+4) = v1b;
        }

        float4 z0a = *(const float4*)(sY + ph0*STRA + r0d);
        float4 z0b = *(const float4*)(sY + ph0*STRA + r0d + 4);
        float4 z1a = *(const float4*)(sY + ph1*STRA + r0d);
        float4 z1b = *(const float4*)(sY + ph1*STRA + r0d + 4);
        z0a = f4_fma(cfr, v0a, z0a); z0b = f4_fma(cfr, v0b, z0b);
        z1a = f4_fma(cfr, v1a, z1a); z1b = f4_fma(cfr, v1b, z1b);
#pragma unroll
        for (int l = 0; l < 5; l++) {
            if (l < s) {
                const float* kb = sK + l * Dd * STRA;
                float4 k0a = *(const float4*)(kb + ph0*STRA + r0d);
                float4 k0b = *(const float4*)(kb + ph0*STRA + r0d + 4);
                float4 k1a = *(const float4*)(kb + ph1*STRA + r0d);
                float4 k1b = *(const float4*)(kb + ph1*STRA + r0d + 4);
                z0a = f4_fma(cf[l], k0a, z0a); z0b = f4_fma(cf[l], k0b, z0b);
                z1a = f4_fma(cf[l], k1a, z1a); z1b = f4_fma(cf[l], k1b, z1b);
            }
        }
        *(float4*)(sZ + ph0*STRA + r0d)     = z0a;
        *(float4*)(sZ + ph0*STRA + r0d + 4) = z0b;
        *(float4*)(sZ + ph1*STRA + r0d)     = z1a;
        *(float4*)(sZ + ph1*STRA + r0d + 4) = z1b;
        if (writeY) {
            *(float4*)(sY + ph0*STRA + r0d)     = z0a;
            *(float4*)(sY + ph0*STRA + r0d + 4) = z0b;
            *(float4*)(sY + ph1*STRA + r0d)     = z1a;
            *(float4*)(sY + ph1*STRA + r0d + 4) = z1b;
        }
    }
}

__global__ void __launch_bounds__(NT, 2)
ffjord_kernel(const float* __restrict__ x, float* __restrict__ out, FfjordParams P)
{
    extern __shared__ float sm[];
    float* sZ   = sm;                          // 64 cols (PHYS6) x STRA
    float* sH1  = sZ + Dd * STRA;              // 256 cols (PHYS8) x STRA
    float* sH2  = sH1 + Hh * STRA;             // 256 cols (PHYS8) x STRA
    float* sY   = sH2 + Hh * STRA;             // 64 cols (PHYS6) x STRA
    float* sK   = sY + Dd * STRA;              // [6][64 cols PHYS6][STRA]
    ulonglong2* sPart = (ulonglong2*)(sK + 6 * Dd * STRA);

    const int tid   = threadIdx.x;
    const int lane  = tid & 31;
    const int w     = tid >> 5;
    const int r0    = (w & 1) * 8;             // dense256 rowgroup
    const int g     = w >> 1;                  // dense256 colgroup
    const int rg    = w & 1;                   // dense64 rowgroup
    const int kg    = w >> 1;                  // dense64 K-group
    const int rbase = blockIdx.x * MROWS;

    for (int i = tid; i < MROWS * Dd; i += NT) {
        int r = i >> 6, d = i & 63;
        float v = x[(rbase + r) * Dd + d];
        int ph = PHYS6(d);
        sY[ph * STRA + r] = v;
        sZ[ph * STRA + r] = v;
    }
    __syncthreads();

    const float h = 1.0f / 16.0f;

    for (int bij = 0; bij < 2; bij++) {
        const float* W1 = P.W1[bij]; const float* b1 = P.b1[bij];
        const float* W2 = P.W2[bij]; const float* b2 = P.b2[bij];
        const float* W3 = P.W3[bij]; const float* b3 = P.b3[bij];
        const float* W1t = W1 + Dd * Hh;       // time row (row 64)

        for (int step = 0; step < NSTEPS; step++) {
            float t0 = (float)step * h;

            for (int s = 0; s < 6; s++) {
                float tstage = t0 + DP_C[s] * h;

                dense256<Dd, INSTEP6, true, true >(W1, b1, W1t, tstage,
                                                   sZ, sH1, lane, g, r0);
                __syncthreads();
                dense256<Hh, INSTEP8, true, false>(W2, b2, nullptr, 0.f,
                                                   sH1, sH2, lane, g, r0);
                __syncthreads();

                float cf[5], cfr;
                bool writeY = (s == 5);
                if (s < 5) {
#pragma unroll
                    for (int l = 0; l < 5; l++) cf[l] = h * DP_A[s+1][l];
                    cfr = h * DP_A[s+1][s];
                } else {
#pragma unroll
                    for (int l = 0; l < 5; l++) cf[l] = h * DP_B[l];
                    cfr = h * DP_B[5];
                }
                dense64_splitk_fused(W3, b3, sH2, sK, sY, sZ, sPart,
                                     cf, cfr, s, writeY, lane, rg, kg);
                __syncthreads();
            }
        }
    }

    for (int i = tid; i < MROWS * Dd; i += NT) {
        int r = i >> 6, d = i & 63;
        out[(rbase + r) * Dd + d] = sY[PHYS6(d) * STRA + r];
    }
}

extern "C" void kernel_launch(void* const* d_in, const int* in_sizes, int n_in,
                              void* d_out, int out_size)
{
    (void)in_sizes; (void)n_in; (void)out_size;
    const float* x = (const float*)d_in[0];

    FfjordParams P;
    P.W1[0] = (const float*)d_in[1];  P.b1[0] = (const float*)d_in[2];
    P.W2[0] = (const float*)d_in[3];  P.b2[0] = (const float*)d_in[4];
    P.W3[0] = (const float*)d_in[5];  P.b3[0] = (const float*)d_in[6];
    P.W1[1] = (const float*)d_in[7];  P.b1[1] = (const float*)d_in[8];
    P.W2[1] = (const float*)d_in[9];  P.b2[1] = (const float*)d_in[10];
    P.W3[1] = (const float*)d_in[11]; P.b3[1] = (const float*)d_in[12];

    static_assert(SM_BYTES <= 100 * 1024, "smem budget (2 CTAs/SM)");
    cudaFuncSetAttribute(ffjord_kernel, cudaFuncAttributeMaxDynamicSharedMemorySize, SM_BYTES);

    ffjord_kernel<<<NCTAS, NT, SM_BYTES>>>(x, (float*)d_out, P);
}

// round 17
// speedup vs baseline: 1.0910x; 1.0910x over previous
#include <cuda_runtime.h>

// FFJORD: 2 chained fixed-step DOPRI5 integrations of a (64+1)->256->256->64 MLP.
// fp32 via fma.rn.f32x2, swizzled conflict-free smem (R16).
// R17: load-balance fix — MROWS=14, grid=296 (exactly 2 CTAs on every SM for
// both 148/152-SM parts). Rowgroup0 = 8 rows (NP=4 pairs), rowgroup1 = 6 rows
// (NP=3). 48 padded rows are guarded at x-load/out-store (rows independent).

typedef unsigned long long u64;

#define Dd     64
#define Hh     256
#define MROWS  14
#define STRA   20      // row stride in floats (float4 alignment + swizzle)
#define NT     128
#define NSTEPS 16
#define NCTAS  296     // 296*14 = 4144 >= 4096
#define NBATCH 4096

#define PHYS6(c) ((((c) & 7) << 3) | ((c) >> 3))
#define INSTEP6  (8  * STRA)
#define INSTEP8  (32 * STRA)

#define SM_FLOATS ((Dd + Hh + Hh + Dd + 6*Dd) * STRA)
#define SM_BYTES  (SM_FLOATS * 4 + 4 * 64 * 16)

struct FfjordParams {
    const float* W1[2]; const float* b1[2];
    const float* W2[2]; const float* b2[2];
    const float* W3[2]; const float* b3[2];
};

__device__ __forceinline__ u64 dup2(float v) {
    u64 r; asm("mov.b64 %0, {%1, %1};" : "=l"(r) : "r"(__float_as_uint(v)));
    return r;
}
__device__ __forceinline__ void fma2(u64& d, u64 a, u64 b) {
    asm("fma.rn.f32x2 %0, %1, %2, %3;" : "=l"(d) : "l"(a), "l"(b), "l"(d));
}
__device__ __forceinline__ u64 add2(u64 a, u64 b) {
    u64 r; asm("add.rn.f32x2 %0, %1, %2;" : "=l"(r) : "l"(a), "l"(b)); return r;
}
__device__ __forceinline__ float lo32(u64 v){ return __uint_as_float((unsigned)v); }
__device__ __forceinline__ float hi32(u64 v){ return __uint_as_float((unsigned)(v>>32)); }

__device__ __forceinline__ float4 ldg4(const float* p) {
    float4 v;
    asm("ld.global.nc.v4.f32 {%0,%1,%2,%3}, [%4];"
        : "=f"(v.x), "=f"(v.y), "=f"(v.z), "=f"(v.w) : "l"(p));
    return v;
}
__device__ __forceinline__ float2 ldg2f(const float* p) {
    float2 v;
    asm("ld.global.nc.v2.f32 {%0,%1}, [%2];" : "=f"(v.x), "=f"(v.y) : "l"(p));
    return v;
}

__device__ __forceinline__ float fast_tanh(float x) {
    float r; asm("tanh.approx.f32 %0, %1;" : "=f"(r) : "f"(x)); return r;
}

__constant__ float DP_A[6][5] = {
    { 0.f, 0.f, 0.f, 0.f, 0.f },
    { 1.f/5.f, 0.f, 0.f, 0.f, 0.f },
    { 3.f/40.f, 9.f/40.f, 0.f, 0.f, 0.f },
    { 44.f/45.f, -56.f/15.f, 32.f/9.f, 0.f, 0.f },
    { 19372.f/6561.f, -25360.f/2187.f, 64448.f/6561.f, -212.f/729.f, 0.f },
    { 9017.f/3168.f, -355.f/33.f, 46732.f/5247.f, 49.f/176.f, -5103.f/18656.f },
};
__constant__ float DP_C[6] = { 0.f, 1.f/5.f, 3.f/10.f, 4.f/5.f, 8.f/9.f, 1.f };
__constant__ float DP_B[6] = { 35.f/384.f, 0.f, 500.f/1113.f, 125.f/192.f,
                               -2187.f/6784.f, 11.f/84.f };

// NP row-pairs (NP=4: 8 rows; NP=3: 6 rows)
template<int NP>
__device__ __forceinline__ void load_abN(u64* dst, const float* p) {
    ulonglong2 t0 = *(const ulonglong2*)(p);
    dst[0] = t0.x; dst[1] = t0.y;
    if (NP == 4) {
        ulonglong2 t1 = *(const ulonglong2*)(p + 4);
        dst[2] = t1.x; dst[3] = t1.y;
    } else {
        dst[2] = *(const u64*)(p + 4);
    }
}
template<int NP>
__device__ __forceinline__ void store_rows(float* base, const float* v) {
    *(float4*)(base) = make_float4(v[0], v[1], v[2], v[3]);
    if (NP == 4) *(float4*)(base + 4) = make_float4(v[4], v[5], v[6], v[7]);
    else         *(float2*)(base + 4) = make_float2(v[4], v[5]);
}
template<int NP>
__device__ __forceinline__ void load_rows(float* v, const float* base) {
    float4 a = *(const float4*)(base);
    v[0] = a.x; v[1] = a.y; v[2] = a.z; v[3] = a.w;
    if (NP == 4) {
        float4 b = *(const float4*)(base + 4);
        v[4] = b.x; v[5] = b.y; v[6] = b.z; v[7] = b.w;
    } else {
        float2 b = *(const float2*)(base + 4);
        v[4] = b.x; v[5] = b.y;
    }
}

// N=256 layer. Warp: rowgroup rg (NP pairs at row r0), colgroup g
// (cols 128*g + 4*lane..+3). Swizzled input (INSTEP) / output (PHYS8).
template<int K, int INSTEP, bool TANH, bool TFOLD, int NP>
__device__ __forceinline__ void dense256(
    const float* __restrict__ W, const float* __restrict__ bias,
    const float* __restrict__ tw, float t,
    const float* __restrict__ sA, float* __restrict__ sOut,
    int lane, int g, int r0)
{
    u64 acc[NP][4];
    {
        float4 b = *(const float4*)(bias + 128*g + 4*lane);
        if (TFOLD) {
            float4 wt = ldg4(tw + 128*g + 4*lane);
            b.x = fmaf(t, wt.x, b.x); b.y = fmaf(t, wt.y, b.y);
            b.z = fmaf(t, wt.z, b.z); b.w = fmaf(t, wt.w, b.w);
        }
        u64 b0 = dup2(b.x), b1 = dup2(b.y), b2 = dup2(b.z), b3 = dup2(b.w);
#pragma unroll
        for (int q = 0; q < NP; q++) {
            acc[q][0] = b0; acc[q][1] = b1; acc[q][2] = b2; acc[q][3] = b3;
        }
    }

    const float* wrow = W + 128*g + 4*lane;
    const float* aBlk = sA + r0;

    float4 wb[8];
#pragma unroll
    for (int s = 0; s < 8; s++) wb[s] = ldg4(wrow + s*Hh);
    const float* wNext = wrow + 8*Hh;

    u64 ab[2][4];
    load_abN<NP>(ab[0], aBlk);
    load_abN<NP>(ab[1], aBlk + INSTEP);

    for (int kb = 0; kb < K - 8; kb += 8) {
#pragma unroll
        for (int i = 0; i < 8; i++) {
            float4 wf = wb[i];
            wb[i] = ldg4(wNext + i*Hh);
            const int pb = i & 1;
            u64 a[4];
#pragma unroll
            for (int q = 0; q < NP; q++) a[q] = ab[pb][q];
            load_abN<NP>(ab[pb], aBlk + ((i+2)&7)*INSTEP + ((i+2)>>3)*STRA);
            u64 wA = dup2(wf.x), wB = dup2(wf.y), wC = dup2(wf.z), wD = dup2(wf.w);
#pragma unroll
            for (int q = 0; q < NP; q++) {
                fma2(acc[q][0], a[q], wA); fma2(acc[q][1], a[q], wB);
                fma2(acc[q][2], a[q], wC); fma2(acc[q][3], a[q], wD);
            }
        }
        wNext += 8*Hh;
        aBlk  += STRA;
    }
#pragma unroll
    for (int i = 0; i < 8; i++) {
        float4 wf = wb[i];
        const int pb = i & 1;
        u64 a[4];
#pragma unroll
        for (int q = 0; q < NP; q++) a[q] = ab[pb][q];
        if (i < 6)
            load_abN<NP>(ab[pb], aBlk + ((i+2)&7)*INSTEP + ((i+2)>>3)*STRA);
        u64 wA = dup2(wf.x), wB = dup2(wf.y), wC = dup2(wf.z), wD = dup2(wf.w);
#pragma unroll
        for (int q = 0; q < NP; q++) {
            fma2(acc[q][0], a[q], wA); fma2(acc[q][1], a[q], wB);
            fma2(acc[q][2], a[q], wC); fma2(acc[q][3], a[q], wD);
        }
    }

    const int pc    = 4 * (lane & 1);
    const int pbase = 16*g + (lane >> 1);
#pragma unroll
    for (int c = 0; c < 4; c++) {
        const int phys = ((pc + c) << 5) + pbase;
        float v[2*NP];
#pragma unroll
        for (int q = 0; q < NP; q++) {
            v[2*q]   = lo32(acc[q][c]);
            v[2*q+1] = hi32(acc[q][c]);
        }
        if (TANH) {
#pragma unroll
            for (int r = 0; r < 2*NP; r++) v[r] = fast_tanh(v[r]);
        }
        store_rows<NP>(sOut + phys*STRA + r0, v);
    }
}

// dense64 GEMM half (no internal sync). acc pre-initialized by caller.
template<int NP>
__device__ __forceinline__ void d64_gemm(
    const float* __restrict__ W, const float* __restrict__ sA,
    u64 acc[4][2], int lane, int kg, int r0d)
{
    const int kbeg = kg * 128;
    const float* wrow = W + kbeg*Dd + 2*lane;
    const float* aBlk = sA + (kbeg >> 3)*STRA + r0d;

    float2 wb[8];
#pragma unroll
    for (int q = 0; q < 8; q++) wb[q] = ldg2f(wrow + q*Dd);
    const float* wNext = wrow + 8*Dd;

    u64 ab[2][4];
    load_abN<NP>(ab[0], aBlk);
    load_abN<NP>(ab[1], aBlk + INSTEP8);

    for (int kb = 0; kb < 120; kb += 8) {
#pragma unroll
        for (int i = 0; i < 8; i++) {
            float2 wf = wb[i];
            wb[i] = ldg2f(wNext + i*Dd);
            const int pb = i & 1;
            u64 a[4];
#pragma unroll
            for (int q = 0; q < NP; q++) a[q] = ab[pb][q];
            load_abN<NP>(ab[pb], aBlk + ((i+2)&7)*INSTEP8 + ((i+2)>>3)*STRA);
            u64 wA = dup2(wf.x), wB = dup2(wf.y);
#pragma unroll
            for (int q = 0; q < NP; q++) {
                fma2(acc[q][0], a[q], wA); fma2(acc[q][1], a[q], wB);
            }
        }
        wNext += 8*Dd;
        aBlk  += STRA;
    }
#pragma unroll
    for (int i = 0; i < 8; i++) {
        float2 wf = wb[i];
        const int pb = i & 1;
        u64 a[4];
#pragma unroll
        for (int q = 0; q < NP; q++) a[q] = ab[pb][q];
        if (i < 6)
            load_abN<NP>(ab[pb], aBlk + ((i+2)&7)*INSTEP8 + ((i+2)>>3)*STRA);
        u64 wA = dup2(wf.x), wB = dup2(wf.y);
#pragma unroll
        for (int q = 0; q < NP; q++) {
            fma2(acc[q][0], a[q], wA); fma2(acc[q][1], a[q], wB);
        }
    }
}

// dense64 reduce + fused RK glue (kg==0 warps only; no internal sync).
template<int NP>
__device__ __forceinline__ void d64_glue(
    u64 acc[4][2], float* __restrict__ sK,
    float* __restrict__ sY, float* __restrict__ sZ,
    const ulonglong2* __restrict__ sPart,
    const float cf[5], float cfr, int s, bool writeY,
    int lane, int rg, int r0d)
{
    const int p = rg*32 + lane;
#pragma unroll
    for (int j = 0; j < NP; j++) {
        ulonglong2 t = sPart[j*64 + p];
        acc[j][0] = add2(acc[j][0], t.x);
        acc[j][1] = add2(acc[j][1], t.y);
    }

    const int ph0 = (((2*lane)     & 7) << 3) | (lane >> 2);
    const int ph1 = (((2*lane + 1) & 7) << 3) | (lane >> 2);

    float v0[2*NP], v1[2*NP];
#pragma unroll
    for (int j = 0; j < NP; j++) {
        v0[2*j] = lo32(acc[j][0]); v0[2*j+1] = hi32(acc[j][0]);
        v1[2*j] = lo32(acc[j][1]); v1[2*j+1] = hi32(acc[j][1]);
    }

    if (s < 5) {
        float* kd = sK + s * Dd * STRA;
        store_rows<NP>(kd + ph0*STRA + r0d, v0);
        store_rows<NP>(kd + ph1*STRA + r0d, v1);
    }

    float z0[2*NP], z1[2*NP];
    load_rows<NP>(z0, sY + ph0*STRA + r0d);
    load_rows<NP>(z1, sY + ph1*STRA + r0d);
#pragma unroll
    for (int e = 0; e < 2*NP; e++) {
        z0[e] = fmaf(cfr, v0[e], z0[e]);
        z1[e] = fmaf(cfr, v1[e], z1[e]);
    }
#pragma unroll
    for (int l = 0; l < 5; l++) {
        if (l < s) {
            const float* kb = sK + l * Dd * STRA;
            float k0[2*NP], k1[2*NP];
            load_rows<NP>(k0, kb + ph0*STRA + r0d);
            load_rows<NP>(k1, kb + ph1*STRA + r0d);
#pragma unroll
            for (int e = 0; e < 2*NP; e++) {
                z0[e] = fmaf(cf[l], k0[e], z0[e]);
                z1[e] = fmaf(cf[l], k1[e], z1[e]);
            }
        }
    }
    store_rows<NP>(sZ + ph0*STRA + r0d, z0);
    store_rows<NP>(sZ + ph1*STRA + r0d, z1);
    if (writeY) {
        store_rows<NP>(sY + ph0*STRA + r0d, z0);
        store_rows<NP>(sY + ph1*STRA + r0d, z1);
    }
}

__global__ void __launch_bounds__(NT, 2)
ffjord_kernel(const float* __restrict__ x, float* __restrict__ out, FfjordParams P)
{
    extern __shared__ float sm[];
    float* sZ   = sm;
    float* sH1  = sZ + Dd * STRA;
    float* sH2  = sH1 + Hh * STRA;
    float* sY   = sH2 + Hh * STRA;
    float* sK   = sY + Dd * STRA;
    ulonglong2* sPart = (ulonglong2*)(sK + 6 * Dd * STRA);

    const int tid   = threadIdx.x;
    const int lane  = tid & 31;
    const int w     = tid >> 5;
    const int rg    = w & 1;                   // rowgroup: 0 -> rows 0-7, 1 -> 8-13
    const int g     = w >> 1;                  // dense256 colgroup
    const int kg    = w >> 1;                  // dense64 K-group
    const int r0    = rg ? 8 : 0;
    const int rbase = blockIdx.x * MROWS;

    for (int i = tid; i < MROWS * Dd; i += NT) {
        int r = i >> 6, d = i & 63;
        int grow = rbase + r;
        float v = (grow < NBATCH) ? x[grow * Dd + d] : 0.0f;
        int ph = PHYS6(d);
        sY[ph * STRA + r] = v;
        sZ[ph * STRA + r] = v;
    }
    __syncthreads();

    const float h = 1.0f / 16.0f;

    for (int bij = 0; bij < 2; bij++) {
        const float* W1 = P.W1[bij]; const float* b1 = P.b1[bij];
        const float* W2 = P.W2[bij]; const float* b2 = P.b2[bij];
        const float* W3 = P.W3[bij]; const float* b3 = P.b3[bij];
        const float* W1t = W1 + Dd * Hh;

        for (int step = 0; step < NSTEPS; step++) {
            float t0 = (float)step * h;

            for (int s = 0; s < 6; s++) {
                float tstage = t0 + DP_C[s] * h;

                if (rg == 0)
                    dense256<Dd, INSTEP6, true, true, 4>(W1, b1, W1t, tstage,
                                                         sZ, sH1, lane, g, 0);
                else
                    dense256<Dd, INSTEP6, true, true, 3>(W1, b1, W1t, tstage,
                                                         sZ, sH1, lane, g, 8);
                __syncthreads();
                if (rg == 0)
                    dense256<Hh, INSTEP8, true, false, 4>(W2, b2, nullptr, 0.f,
                                                          sH1, sH2, lane, g, 0);
                else
                    dense256<Hh, INSTEP8, true, false, 3>(W2, b2, nullptr, 0.f,
                                                          sH1, sH2, lane, g, 8);
                __syncthreads();

                float cf[5], cfr;
                bool writeY = (s == 5);
                if (s < 5) {
#pragma unroll
                    for (int l = 0; l < 5; l++) cf[l] = h * DP_A[s+1][l];
                    cfr = h * DP_A[s+1][s];
                } else {
#pragma unroll
                    for (int l = 0; l < 5; l++) cf[l] = h * DP_B[l];
                    cfr = h * DP_B[5];
                }

                // dense64: GEMM -> partial store -> sync -> reduce+glue
                u64 acc64[4][2];
                if (kg == 0) {
                    float2 bb = *(const float2*)(b3 + 2*lane);
                    u64 b0 = dup2(bb.x), b1v = dup2(bb.y);
#pragma unroll
                    for (int q = 0; q < 4; q++) { acc64[q][0] = b0; acc64[q][1] = b1v; }
                } else {
#pragma unroll
                    for (int q = 0; q < 4; q++) { acc64[q][0] = 0ull; acc64[q][1] = 0ull; }
                }
                if (rg == 0) d64_gemm<4>(W3, sH2, acc64, lane, kg, 0);
                else         d64_gemm<3>(W3, sH2, acc64, lane, kg, 8);

                if (kg == 1) {
                    const int p  = rg*32 + lane;
                    const int np = rg ? 3 : 4;
                    for (int j = 0; j < np; j++)
                        sPart[j*64 + p] = make_ulonglong2(acc64[j][0], acc64[j][1]);
                }
                __syncthreads();
                if (kg == 0) {
                    if (rg == 0)
                        d64_glue<4>(acc64, sK, sY, sZ, sPart, cf, cfr, s, writeY,
                                    lane, rg, 0);
                    else
                        d64_glue<3>(acc64, sK, sY, sZ, sPart, cf, cfr, s, writeY,
                                    lane, rg, 8);
                }
                __syncthreads();
            }
        }
    }

    for (int i = tid; i < MROWS * Dd; i += NT) {
        int r = i >> 6, d = i & 63;
        int grow = rbase + r;
        if (grow < NBATCH)
            out[grow * Dd + d] = sY[PHYS6(d) * STRA + r];
    }
}

extern "C" void kernel_launch(void* const* d_in, const int* in_sizes, int n_in,
                              void* d_out, int out_size)
{
    (void)in_sizes; (void)n_in; (void)out_size;
    const float* x = (const float*)d_in[0];

    FfjordParams P;
    P.W1[0] = (const float*)d_in[1];  P.b1[0] = (const float*)d_in[2];
    P.W2[0] = (const float*)d_in[3];  P.b2[0] = (const float*)d_in[4];
    P.W3[0] = (const float*)d_in[5];  P.b3[0] = (const float*)d_in[6];
    P.W1[1] = (const float*)d_in[7];  P.b1[1] = (const float*)d_in[8];
    P.W2[1] = (const float*)d_in[9];  P.b2[1] = (const float*)d_in[10];
    P.W3[1] = (const float*)d_in[11]; P.b3[1] = (const float*)d_in[12];

    static_assert(SM_BYTES <= 100 * 1024, "smem budget (2 CTAs/SM)");
    cudaFuncSetAttribute(ffjord_kernel, cudaFuncAttributeMaxDynamicSharedMemorySize, SM_BYTES);

    ffjord_kernel<<<NCTAS, NT, SM_BYTES>>>(x, (float*)d_out, P);
}